// round 2
// baseline (speedup 1.0000x reference)
#include <cuda_runtime.h>
#include <math.h>

#define DD   1024
#define NE   100
#define BT   32768   // 8*4096

// ---------------- device scratch ----------------
__device__ float g_cnorm[128 * DD];             // normalized centroids, zero-padded to 128 rows
__device__ float g_apad[(size_t)BT * 128];      // assignment, padded to 128 entities
__device__ float g_wpart[256 * 128];            // per-block weight partials
__device__ float g_weights[8 * 128];            // sum over T + 1e-6
__device__ float g_efpart[(size_t)4 * 8 * 128 * DD]; // split-K partials for GEMM2

// ---------------- packed fp32x2 helpers (sm_103a) ----------------
__device__ __forceinline__ unsigned long long pk2(float lo, float hi) {
    unsigned long long r;
    asm("mov.b64 %0, {%1, %2};" : "=l"(r) : "f"(lo), "f"(hi));
    return r;
}
__device__ __forceinline__ void fma2(unsigned long long& d, unsigned long long a, unsigned long long b) {
    asm("fma.rn.f32x2 %0, %1, %2, %0;" : "+l"(d) : "l"(a), "l"(b));
}
__device__ __forceinline__ float2 upk(unsigned long long v) {
    float2 r;
    asm("mov.b64 {%0, %1}, %2;" : "=f"(r.x), "=f"(r.y) : "l"(v));
    return r;
}

// 16-step K inner product. US: broadcast side rows ty*8..+7. VS: pair side cols tx*4.. and 64+tx*4..
#define INNER16(US, VS)                                                                             \
    _Pragma("unroll")                                                                               \
    for (int kk = 0; kk < 16; ++kk) {                                                               \
        float4 u0 = *(const float4*)&US[kk][ty * 8];                                                \
        float4 u1 = *(const float4*)&US[kk][ty * 8 + 4];                                            \
        float4 v0 = *(const float4*)&VS[kk][tx * 4];                                                \
        float4 v1 = *(const float4*)&VS[kk][64 + tx * 4];                                           \
        unsigned long long vp0 = pk2(v0.x, v0.y), vp1 = pk2(v0.z, v0.w);                            \
        unsigned long long vp2 = pk2(v1.x, v1.y), vp3 = pk2(v1.z, v1.w);                            \
        unsigned long long ud;                                                                      \
        ud = pk2(u0.x, u0.x); fma2(acc[0][0], ud, vp0); fma2(acc[0][1], ud, vp1);                   \
                              fma2(acc[0][2], ud, vp2); fma2(acc[0][3], ud, vp3);                   \
        ud = pk2(u0.y, u0.y); fma2(acc[1][0], ud, vp0); fma2(acc[1][1], ud, vp1);                   \
                              fma2(acc[1][2], ud, vp2); fma2(acc[1][3], ud, vp3);                   \
        ud = pk2(u0.z, u0.z); fma2(acc[2][0], ud, vp0); fma2(acc[2][1], ud, vp1);                   \
                              fma2(acc[2][2], ud, vp2); fma2(acc[2][3], ud, vp3);                   \
        ud = pk2(u0.w, u0.w); fma2(acc[3][0], ud, vp0); fma2(acc[3][1], ud, vp1);                   \
                              fma2(acc[3][2], ud, vp2); fma2(acc[3][3], ud, vp3);                   \
        ud = pk2(u1.x, u1.x); fma2(acc[4][0], ud, vp0); fma2(acc[4][1], ud, vp1);                   \
                              fma2(acc[4][2], ud, vp2); fma2(acc[4][3], ud, vp3);                   \
        ud = pk2(u1.y, u1.y); fma2(acc[5][0], ud, vp0); fma2(acc[5][1], ud, vp1);                   \
                              fma2(acc[5][2], ud, vp2); fma2(acc[5][3], ud, vp3);                   \
        ud = pk2(u1.z, u1.z); fma2(acc[6][0], ud, vp0); fma2(acc[6][1], ud, vp1);                   \
                              fma2(acc[6][2], ud, vp2); fma2(acc[6][3], ud, vp3);                   \
        ud = pk2(u1.w, u1.w); fma2(acc[7][0], ud, vp0); fma2(acc[7][1], ud, vp1);                   \
                              fma2(acc[7][2], ud, vp2); fma2(acc[7][3], ud, vp3);                   \
    }

// ---------------- kernel 0: normalize centroids, zero-pad to 128 rows ----------------
__global__ void __launch_bounds__(256) k_cnorm(const float* __restrict__ cent) {
    int e = blockIdx.x;            // 0..127
    int tid = threadIdx.x;         // 256 threads, 1 float4 each
    float4* dst = (float4*)(g_cnorm + (size_t)e * DD);
    if (e >= NE) { dst[tid] = make_float4(0.f, 0.f, 0.f, 0.f); return; }
    __shared__ float warps[8];
    float4 a = ((const float4*)(cent + (size_t)e * DD))[tid];
    float ss = a.x * a.x + a.y * a.y + a.z * a.z + a.w * a.w;
#pragma unroll
    for (int m = 16; m; m >>= 1) ss += __shfl_xor_sync(0xffffffffu, ss, m);
    if ((tid & 31) == 0) warps[tid >> 5] = ss;
    __syncthreads();
    float tot = 0.f;
#pragma unroll
    for (int w = 0; w < 8; ++w) tot += warps[w];
    float inv = 1.0f / fmaxf(sqrtf(tot), 1e-12f);
    dst[tid] = make_float4(a.x * inv, a.y * inv, a.z * inv, a.w * inv);
}

// ---------------- kernel 1: sim GEMM + softmax + assignment + weight partials ----------------
__global__ void __launch_bounds__(256) k_sim(const float* __restrict__ tokens,
                                             float* __restrict__ aout) {
    __shared__ __align__(16) float As[16][132];   // [k][token m]
    __shared__ __align__(16) float Bs[16][132];   // [k][entity n]
    __shared__ float snorm[128];
    __shared__ float wsum[16][132];

    int tid = threadIdx.x;
    int tx = tid & 15, ty = tid >> 4;
    int blk = blockIdx.x;
    size_t row0 = (size_t)blk << 7;               // 128 tokens per block

    int lm = tid & 127;                           // row within tile
    int lk = (tid >> 7) << 3;                     // k offset: 0 or 8

    const float* Ap = tokens + (row0 + lm) * DD + lk;
    const float* Bp = g_cnorm + (size_t)lm * DD + lk;

    unsigned long long acc[8][4];
#pragma unroll
    for (int i = 0; i < 8; ++i)
#pragma unroll
        for (int p = 0; p < 4; ++p) acc[i][p] = 0ull;

    float ss = 0.f;
    float4 a0 = *(const float4*)Ap;
    float4 a1 = *(const float4*)(Ap + 4);
    float4 b0 = *(const float4*)Bp;
    float4 b1 = *(const float4*)(Bp + 4);

    for (int c = 0; c < 64; ++c) {
        As[lk + 0][lm] = a0.x; As[lk + 1][lm] = a0.y; As[lk + 2][lm] = a0.z; As[lk + 3][lm] = a0.w;
        As[lk + 4][lm] = a1.x; As[lk + 5][lm] = a1.y; As[lk + 6][lm] = a1.z; As[lk + 7][lm] = a1.w;
        Bs[lk + 0][lm] = b0.x; Bs[lk + 1][lm] = b0.y; Bs[lk + 2][lm] = b0.z; Bs[lk + 3][lm] = b0.w;
        Bs[lk + 4][lm] = b1.x; Bs[lk + 5][lm] = b1.y; Bs[lk + 6][lm] = b1.z; Bs[lk + 7][lm] = b1.w;
        ss += a0.x * a0.x + a0.y * a0.y + a0.z * a0.z + a0.w * a0.w
            + a1.x * a1.x + a1.y * a1.y + a1.z * a1.z + a1.w * a1.w;
        __syncthreads();
        if (c < 63) {                              // prefetch next chunk (overlaps INNER16)
            int off = (c + 1) << 4;
            a0 = *(const float4*)(Ap + off);
            a1 = *(const float4*)(Ap + off + 4);
            b0 = *(const float4*)(Bp + off);
            b1 = *(const float4*)(Bp + off + 4);
        }
        INNER16(As, Bs)
        __syncthreads();
    }

    // token sum-of-squares: row lm covered by tid=lm (k 0..7 of each chunk) and tid=lm+128 (k 8..15)
    if (tid < 128) snorm[tid] = ss;
    __syncthreads();
    if (tid >= 128) snorm[tid - 128] += ss;
    __syncthreads();

    bool g1 = (tx < 9);   // second entity group valid only when 64+tx*4+3 < 100
    float pr[8][8];
#pragma unroll
    for (int i = 0; i < 8; ++i) {
        float sc = 10.0f / fmaxf(sqrtf(snorm[ty * 8 + i]), 1e-12f);  // (1/T)/max(||x||,eps)
#pragma unroll
        for (int pp = 0; pp < 4; ++pp) {
            float2 f = upk(acc[i][pp]);
            pr[i][pp * 2 + 0] = f.x * sc;
            pr[i][pp * 2 + 1] = f.y * sc;
        }
    }

    float w0[4] = {0.f, 0.f, 0.f, 0.f}, w1[4] = {0.f, 0.f, 0.f, 0.f};
#pragma unroll
    for (int i = 0; i < 8; ++i) {
        float mx = fmaxf(fmaxf(pr[i][0], pr[i][1]), fmaxf(pr[i][2], pr[i][3]));
        if (g1) mx = fmaxf(mx, fmaxf(fmaxf(pr[i][4], pr[i][5]), fmaxf(pr[i][6], pr[i][7])));
        mx = fmaxf(mx, __shfl_xor_sync(0xffffffffu, mx, 1));
        mx = fmaxf(mx, __shfl_xor_sync(0xffffffffu, mx, 2));
        mx = fmaxf(mx, __shfl_xor_sync(0xffffffffu, mx, 4));
        mx = fmaxf(mx, __shfl_xor_sync(0xffffffffu, mx, 8));
        float sum = 0.f;
#pragma unroll
        for (int n = 0; n < 8; ++n) {
            float t = (n < 4 || g1) ? __expf(pr[i][n] - mx) : 0.f;
            pr[i][n] = t;
            sum += t;
        }
        sum += __shfl_xor_sync(0xffffffffu, sum, 1);
        sum += __shfl_xor_sync(0xffffffffu, sum, 2);
        sum += __shfl_xor_sync(0xffffffffu, sum, 4);
        sum += __shfl_xor_sync(0xffffffffu, sum, 8);
        float inv = 1.0f / sum;
#pragma unroll
        for (int n = 0; n < 8; ++n) pr[i][n] *= inv;

        size_t trow = row0 + (size_t)ty * 8 + i;
        float* rp = aout + trow * NE;
        *(float4*)(rp + tx * 4) = make_float4(pr[i][0], pr[i][1], pr[i][2], pr[i][3]);
        if (g1) *(float4*)(rp + 64 + tx * 4) = make_float4(pr[i][4], pr[i][5], pr[i][6], pr[i][7]);

        float* ap = g_apad + trow * 128;
        *(float4*)(ap + tx * 4) = make_float4(pr[i][0], pr[i][1], pr[i][2], pr[i][3]);
        *(float4*)(ap + 64 + tx * 4) = make_float4(pr[i][4], pr[i][5], pr[i][6], pr[i][7]);

#pragma unroll
        for (int n = 0; n < 4; ++n) { w0[n] += pr[i][n]; w1[n] += pr[i][n + 4]; }
    }

    // per-block entity weight partials
#pragma unroll
    for (int j = 0; j < 4; ++j) {
        wsum[ty][tx * 4 + j] = w0[j];
        wsum[ty][64 + tx * 4 + j] = w1[j];
    }
    __syncthreads();
    if (tid < 128) {
        float s = 0.f;
#pragma unroll
        for (int w = 0; w < 16; ++w) s += wsum[w][tid];
        g_wpart[blk * 128 + tid] = s;
    }
}

// ---------------- kernel 2: weight reduce ----------------
__global__ void __launch_bounds__(1024) k_wred() {
    int tid = threadIdx.x;         // 1024 = 8 batches * 128 entities
    int b = tid >> 7, e = tid & 127;
    float s = 1e-6f;
#pragma unroll
    for (int j = 0; j < 32; ++j) s += g_wpart[(b * 32 + j) * 128 + e];
    g_weights[tid] = s;
}

// ---------------- kernel 3: entity_features GEMM (split-K=4) ----------------
__global__ void __launch_bounds__(256) k_ef(const float* __restrict__ tokens) {
    __shared__ __align__(16) float As[16][132];   // [k][entity]
    __shared__ __align__(16) float Bs[16][132];   // [k][d]

    int tid = threadIdx.x;
    int tx = tid & 15, ty = tid >> 4;
    int bid = blockIdx.x;
    int dt = bid & 7;              // d tile
    int b  = (bid >> 3) & 7;       // batch
    int s  = bid >> 6;             // split 0..3
    size_t tok0 = (size_t)b * 4096 + (size_t)s * 1024;

    int k = tid >> 4;              // 0..15
    int f = tid & 15;
    const float* Apt = g_apad + (tok0 + k) * 128 + f * 4;
    const float* Bpt = tokens + (tok0 + k) * DD + (size_t)dt * 128 + f * 4;

    unsigned long long acc[8][4];
#pragma unroll
    for (int i = 0; i < 8; ++i)
#pragma unroll
        for (int p = 0; p < 4; ++p) acc[i][p] = 0ull;

    float4 a0 = *(const float4*)Apt;
    float4 a1 = *(const float4*)(Apt + 64);
    float4 b0 = *(const float4*)Bpt;
    float4 b1 = *(const float4*)(Bpt + 64);

    for (int c = 0; c < 64; ++c) {
        *(float4*)&As[k][f * 4]      = a0;
        *(float4*)&As[k][f * 4 + 64] = a1;
        *(float4*)&Bs[k][f * 4]      = b0;
        *(float4*)&Bs[k][f * 4 + 64] = b1;
        __syncthreads();
        if (c < 63) {
            size_t offA = (size_t)(c + 1) * 16 * 128;
            size_t offB = (size_t)(c + 1) * 16 * DD;
            a0 = *(const float4*)(Apt + offA);
            a1 = *(const float4*)(Apt + offA + 64);
            b0 = *(const float4*)(Bpt + offB);
            b1 = *(const float4*)(Bpt + offB + 64);
        }
        INNER16(As, Bs)
        __syncthreads();
    }

    float* op = g_efpart + ((size_t)(s * 8 + b) * 128) * DD + (size_t)dt * 128;
#pragma unroll
    for (int i = 0; i < 8; ++i) {
        int e = ty * 8 + i;
        float2 f0 = upk(acc[i][0]), f1 = upk(acc[i][1]);
        float2 f2 = upk(acc[i][2]), f3 = upk(acc[i][3]);
        *(float4*)(op + (size_t)e * DD + tx * 4)      = make_float4(f0.x, f0.y, f1.x, f1.y);
        *(float4*)(op + (size_t)e * DD + 64 + tx * 4) = make_float4(f2.x, f2.y, f3.x, f3.y);
    }
}

// ---------------- kernel 4: combine splits + divide by weights ----------------
__global__ void __launch_bounds__(256) k_combine(float* __restrict__ efout) {
    int gid = blockIdx.x * 256 + threadIdx.x;     // float4 index, 0..204799
    int d4 = gid & 255;
    int be = gid >> 8;                            // b*100 + e
    int e = be % 100;
    int b = be / 100;
    const float4* p = (const float4*)g_efpart;
    size_t idx = ((size_t)b * 128 + e) * 256 + d4;
    size_t sstr = (size_t)8 * 128 * 256;
    float4 v = p[idx];
    float4 t;
    t = p[idx + sstr];     v.x += t.x; v.y += t.y; v.z += t.z; v.w += t.w;
    t = p[idx + 2 * sstr]; v.x += t.x; v.y += t.y; v.z += t.z; v.w += t.w;
    t = p[idx + 3 * sstr]; v.x += t.x; v.y += t.y; v.z += t.z; v.w += t.w;
    float inv = 1.0f / g_weights[b * 128 + e];
    ((float4*)efout)[gid] = make_float4(v.x * inv, v.y * inv, v.z * inv, v.w * inv);
}

extern "C" void kernel_launch(void* const* d_in, const int* in_sizes, int n_in,
                              void* d_out, int out_size) {
    const float* tokens = (const float*)d_in[0];   // (8,4096,1024)
    const float* cent   = (const float*)d_in[1];   // (100,1024)
    float* out = (float*)d_out;                    // assignment | entity_features

    k_cnorm<<<128, 256>>>(cent);
    k_sim<<<256, 256>>>(tokens, out);
    k_wred<<<1, 1024>>>();
    k_ef<<<256, 256>>>(tokens);
    k_combine<<<800, 256>>>(out + (size_t)BT * NE);
}